// round 10
// baseline (speedup 1.0000x reference)
#include <cuda_runtime.h>
#include <cuda_fp16.h>
#include <math.h>

#define L     4096
#define NF    4097
#define NFFT  8192
#define KF    40
#define FE    32
#define NEB   129        // einsum blocks
#define ARB   256        // AR blocks
#define AR_T  32

// ---------------- static device scratch ----------------
__device__ float2 g_Xf[2 * NF * 64];
__device__ float2 g_vf[NF * KF];
__device__ float2 g_Sp[2 * NF * 64];
__device__ float2 g_Sm[2 * NF * 64];

// ---------------- helpers ----------------
__device__ __forceinline__ unsigned brev13(unsigned i) { return __brev(i) >> 19; }
__device__ __forceinline__ unsigned s2u(const void* p) { return (unsigned)__cvta_generic_to_shared(p); }

__device__ __forceinline__ float2 cadd(float2 a, float2 b) { return make_float2(a.x + b.x, a.y + b.y); }
__device__ __forceinline__ float2 csub(float2 a, float2 b) { return make_float2(a.x - b.x, a.y - b.y); }
__device__ __forceinline__ float2 cmul(float2 a, float2 b) {
    return make_float2(a.x * b.x - a.y * b.y, a.x * b.y + a.y * b.x);
}

__device__ __forceinline__ void mma16(float& d0, float& d1, float& d2, float& d3,
                                      unsigned a0, unsigned a1, unsigned a2, unsigned a3,
                                      unsigned b0, unsigned b1) {
    asm("mma.sync.aligned.m16n8k16.row.col.f32.f16.f16.f32 "
        "{%0,%1,%2,%3},{%4,%5,%6,%7},{%8,%9},{%0,%1,%2,%3};"
        : "+f"(d0), "+f"(d1), "+f"(d2), "+f"(d3)
        : "r"(a0), "r"(a1), "r"(a2), "r"(a3), "r"(b0), "r"(b1));
}
__device__ __forceinline__ void ldsm4(unsigned* r, unsigned a) {
    asm volatile("ldmatrix.sync.aligned.m8n8.x4.shared.b16 {%0,%1,%2,%3}, [%4];"
                 : "=r"(r[0]), "=r"(r[1]), "=r"(r[2]), "=r"(r[3]) : "r"(a));
}
__device__ __forceinline__ void ldsm2t(unsigned& r0, unsigned& r1, unsigned a) {
    asm volatile("ldmatrix.sync.aligned.m8n8.x2.trans.shared.b16 {%0,%1}, [%2];"
                 : "=r"(r0), "=r"(r1) : "r"(a));
}

// In-place FFT of 8192 (bit-reversed input): 1 radix-2 stage + 6 fused radix-4
// passes -> 7 smem round-trips instead of 13. SIGN = -1 fwd, +1 inv; tw built
// to match: tw[i] = (cos, SIGN*sin)(pi*i/4096).
template<int NT>
__device__ __forceinline__ void fftR4(float2* s, const float2* tw, const float SIGN) {
    for (int j = threadIdx.x; j < 4096; j += NT) {
        int i0 = j << 1, i1 = i0 + 1;
        float2 u = s[i0], v = s[i1];
        s[i0] = cadd(u, v);
        s[i1] = csub(u, v);
    }
    __syncthreads();
    #pragma unroll
    for (int st = 1; st < 13; st += 2) {
        const int h = 1 << st;
        for (int j = threadIdx.x; j < 2048; j += NT) {
            int pos = j & (h - 1);
            int base = (j >> st) << (st + 2);
            int i0 = base + pos, i1 = i0 + h, i2 = i0 + 2 * h, i3 = i0 + 3 * h;
            float2 t1 = tw[pos << (12 - st)];
            float2 t2 = tw[pos << (11 - st)];
            float2 u0 = s[i0], u1 = s[i1], u2 = s[i2], u3 = s[i3];
            float2 c1 = cmul(t1, u1);
            float2 a0 = cadd(u0, c1), a1 = csub(u0, c1);
            float2 c3 = cmul(t1, u3);
            float2 a2 = cadd(u2, c3), a3 = csub(u2, c3);
            float2 d2 = cmul(t2, a2);
            float2 d3 = cmul(t2, a3);
            float2 d3p = make_float2(-SIGN * d3.y, SIGN * d3.x);
            s[i0] = cadd(a0, d2);  s[i2] = csub(a0, d2);
            s[i1] = cadd(a1, d3p); s[i3] = csub(a1, d3p);
        }
        __syncthreads();
    }
}

// ---------------- K1: forward FFTs of x (64 blocks) and phi (20 blocks) ----------------
__global__ __launch_bounds__(1024) void k_fwd(const float* __restrict__ x,
                                              const float* __restrict__ phi) {
    extern __shared__ float2 s[];
    float2* tw = s + NFFT;
    for (int i = threadIdx.x; i < 4096; i += 1024) {
        float sv, cv;
        __sincosf(3.14159265358979323846f * (float)i / 4096.0f, &sv, &cv);
        tw[i] = make_float2(cv, -sv);
    }
    const int bb = blockIdx.x;
    const float* src;
    int strd, c0;
    if (bb < 64) { int b = bb >> 5; c0 = (bb & 31) * 2; src = x + (size_t)b * L * 64 + c0; strd = 64; }
    else         { c0 = (bb - 64) * 2; src = phi + c0; strd = KF; }

    for (int i = threadIdx.x; i < NFFT; i += 1024) {
        float2 z = make_float2(0.f, 0.f);
        if (i < L) z = *(const float2*)(src + (size_t)i * strd);
        s[brev13(i)] = z;
    }
    __syncthreads();
    fftR4<1024>(s, tw, -1.f);

    for (int f = threadIdx.x; f <= L; f += 1024) {
        float2 P = s[f], Q = s[(NFFT - f) & (NFFT - 1)];
        float qr = Q.x, qi = -Q.y;
        float4 o = make_float4(0.5f * (P.x + qr), 0.5f * (P.y + qi),
                               0.5f * (P.y - qi), -0.5f * (P.x - qr));
        if (bb < 64) { int b = bb >> 5; *(float4*)&g_Xf[((size_t)b * NF + f) * 64 + c0] = o; }
        else         { *(float4*)&g_vf[(size_t)f * KF + c0] = o; }
    }
}

// ---------------- K2 fused: einsum (blocks 0..128) + AR term (blocks 129..384) ----------------
#define SAH 72
#define SBH 72
#define OFF_AL 18432
#define OFF_B  36864
#define OFF_V  55296
#define FU_SMEM 65536

__device__ __forceinline__ void einsum_block(char* smc, int ebid,
                                             const float* __restrict__ Mp,
                                             const float* __restrict__ Mm) {
    __half* Ah = (__half*)smc;
    __half* Al = (__half*)(smc + OFF_AL);
    __half* Bs = (__half*)(smc + OFF_B);
    float2* Vs = (float2*)(smc + OFF_V);
    const unsigned smb = s2u(smc);
    const int tid = threadIdx.x, w = tid >> 5, lane = tid & 31, g = lane >> 2, tg = lane & 3;
    const int f0 = ebid * FE;

    for (int idx = tid; idx < FE * KF; idx += 256) {
        int fl = idx / KF, k = idx - fl * KF, f = f0 + fl;
        Vs[idx] = (f <= L) ? g_vf[(size_t)f * KF + k] : make_float2(0.f, 0.f);
    }

    const int p = 8 * w + g, pfl = p & 31, pb = p >> 5, pf = f0 + pfl;
    const unsigned aoff = 2u * ((unsigned)(w * 16 + ((lane >> 3) & 1) * 8 + (lane & 7)) * SAH
                                + (unsigned)(lane >> 4) * 8);
    const unsigned brow = (unsigned)((lane & 8) + (lane & 7));

    for (int br = 0; br < 2; ++br) {
        const float* Mb = br ? Mm : Mp;
        __syncthreads();

        for (int idx = tid; idx < 4096; idx += 256) {
            int pp = idx >> 6, d = idx & 63;
            int b = pp >> 5, fl = pp & 31, f = f0 + fl;
            float re = 0.f, im = 0.f;
            if (f <= L) {
                float2 X;
                if (br == 0) { X = g_Xf[((size_t)b * NF + f) * 64 + d];       re = X.x; im = X.y;  }
                else         { X = g_Xf[((size_t)b * NF + (L - f)) * 64 + d]; re = X.x; im = -X.y; }
            }
            int rr = ((pp >> 3) << 4) + (pp & 7);
            __half h = __float2half_rn(re);
            Ah[rr * SAH + d] = h;
            Al[rr * SAH + d] = __float2half_rn(re - __half2float(h));
            h = __float2half_rn(im);
            Ah[(rr + 8) * SAH + d] = h;
            Al[(rr + 8) * SAH + d] = __float2half_rn(im - __half2float(h));
        }
        __syncthreads();

        unsigned ah[4][4], al[4][4];
        #pragma unroll
        for (int ks = 0; ks < 4; ++ks) {
            ldsm4(ah[ks], smb + aoff + 32u * ks);
            ldsm4(al[ks], smb + OFF_AL + aoff + 32u * ks);
        }

        float S[8][4];
        #pragma unroll
        for (int nt = 0; nt < 8; ++nt)
            S[nt][0] = S[nt][1] = S[nt][2] = S[nt][3] = 0.f;

        #pragma unroll
        for (int i = 0; i < 4; ++i) {
            int e = (tid + i * 256) * 4;
            float4 v4 = *(const float4*)(Mb + e);
            __half2 p0 = __floats2half2_rn(v4.x, v4.y);
            __half2 p1 = __floats2half2_rn(v4.z, v4.w);
            *(uint2*)(Bs + (e >> 6) * SBH + (e & 63)) = make_uint2(*(unsigned*)&p0, *(unsigned*)&p1);
        }
        __syncthreads();

        for (int k = 0; k < KF; ++k) {
            const int cur = k & 1;
            float4 pf4[4];
            if (k + 1 < KF) {
                const float* src2 = Mb + (size_t)(k + 1) * 4096;
                #pragma unroll
                for (int i = 0; i < 4; ++i) pf4[i] = *(const float4*)(src2 + (tid + i * 256) * 4);
            }
            const unsigned bbase = smb + OFF_B + (unsigned)cur * 9216u;
            const float2 v = (pf <= L) ? Vs[pfl * KF + k] : make_float2(0.f, 0.f);

            #pragma unroll
            for (int nt = 0; nt < 8; ++nt) {
                float t0 = 0.f, t1 = 0.f, t2 = 0.f, t3 = 0.f;
                #pragma unroll
                for (int ks = 0; ks < 4; ++ks) {
                    unsigned b0, b1;
                    ldsm2t(b0, b1, bbase + 2u * ((16u * ks + brow) * SBH + 8u * nt));
                    mma16(t0, t1, t2, t3, ah[ks][0], ah[ks][1], ah[ks][2], ah[ks][3], b0, b1);
                    mma16(t0, t1, t2, t3, al[ks][0], al[ks][1], al[ks][2], al[ks][3], b0, b1);
                }
                S[nt][0] += v.x * t0 - v.y * t2;
                S[nt][1] += v.x * t1 - v.y * t3;
                S[nt][2] += v.x * t2 + v.y * t0;
                S[nt][3] += v.x * t3 + v.y * t1;
            }

            if (k + 1 < KF) {
                __half* Bn = Bs + (cur ^ 1) * 4608;
                #pragma unroll
                for (int i = 0; i < 4; ++i) {
                    int e = (tid + i * 256) * 4;
                    __half2 p0 = __floats2half2_rn(pf4[i].x, pf4[i].y);
                    __half2 p1 = __floats2half2_rn(pf4[i].z, pf4[i].w);
                    *(uint2*)(Bn + (e >> 6) * SBH + (e & 63)) = make_uint2(*(unsigned*)&p0, *(unsigned*)&p1);
                }
            }
            __syncthreads();
        }

        if (pf <= L) {
            float2* Sg = (br ? g_Sm : g_Sp) + ((size_t)pb * NF + pf) * 64;
            #pragma unroll
            for (int nt = 0; nt < 8; ++nt) {
                int o = 8 * nt + 2 * tg;
                Sg[o]     = make_float2(S[nt][0], S[nt][2]);
                Sg[o + 1] = make_float2(S[nt][1], S[nt][3]);
            }
        }
    }
}

// AR blocks WRITE out (k_ifft later accumulates on top).
__device__ __forceinline__ void ar_block(char* smc, int abid,
                                         const float* __restrict__ x,
                                         const float* __restrict__ M,
                                         float* __restrict__ out) {
    float* Ms = (float*)smc;                 // [3][64][64]
    float* xs = Ms + 12288;                  // [AR_T+2][64]
    const int b  = abid >> 7;                // 128 blocks per batch
    const int t0 = (abid & 127) * AR_T;
    const int tid = threadIdx.x;

    for (int idx = tid; idx < 12288; idx += 256) {
        int o = idx / 192, r = idx - o * 192;
        int d = r / 3, i = r - d * 3;
        Ms[(i * 64 + d) * 64 + o] = M[idx];
    }
    for (int idx = tid; idx < (AR_T + 2) * 64; idx += 256) {
        int r = idx >> 6, d = idx & 63;
        int t = t0 - 2 + r;
        xs[idx] = (t >= 0) ? x[((size_t)b * L + t) * 64 + d] : 0.f;
    }
    __syncthreads();

    const int o  = tid & 63;
    const int tq = tid >> 6;
    for (int tl = tq; tl < AR_T; tl += 4) {
        const float* x0 = xs + (tl + 2) * 64;
        const float* x1 = x0 - 64;
        const float* x2 = x0 - 128;
        float acc = 0.f;
        #pragma unroll 16
        for (int d = 0; d < 64; ++d) {
            acc += Ms[d * 64 + o]        * x0[d];
            acc += Ms[4096 + d * 64 + o] * x1[d];
            acc += Ms[8192 + d * 64 + o] * x2[d];
        }
        out[((size_t)b * L + t0 + tl) * 64 + o] = acc;
    }
}

__global__ __launch_bounds__(256, 1)
void k_fused(const float* __restrict__ Mp, const float* __restrict__ Mm,
             const float* __restrict__ x,  const float* __restrict__ M,
             float* __restrict__ out) {
    extern __shared__ char smc[];
    if (blockIdx.x < NEB) einsum_block(smc, blockIdx.x, Mp, Mm);
    else                  ar_block(smc, blockIdx.x - NEB, x, M, out);
}

// ---------------- K3: inverse FFT; accumulates onto AR-initialized out ----------------
__global__ __launch_bounds__(1024) void k_ifft(float* __restrict__ out) {
    extern __shared__ float2 s[];
    float2* tw = s + NFFT;
    for (int i = threadIdx.x; i < 4096; i += 1024) {
        float sv, cv;
        __sincosf(3.14159265358979323846f * (float)i / 4096.0f, &sv, &cv);
        tw[i] = make_float2(cv, sv);
    }
    const int b = blockIdx.x >> 6, o = blockIdx.x & 63;
    const float2* spb = g_Sp + (size_t)b * NF * 64 + o;
    const float2* smb = g_Sm + (size_t)b * NF * 64 + o;

    for (int f = threadIdx.x; f < NFFT; f += 1024) {
        float2 C;
        if (f <= L) {
            float2 p = spb[(size_t)f * 64], m = smb[(size_t)f * 64];
            C = make_float2(p.x - m.y, p.y + m.x);
        } else {
            int gi = NFFT - f;
            float2 p = spb[(size_t)gi * 64], m = smb[(size_t)gi * 64];
            C = make_float2(p.x + m.y, m.x - p.y);
        }
        s[brev13(f)] = C;
    }
    __syncthreads();
    fftR4<1024>(s, tw, 1.f);

    const float inv = 1.0f / 8192.0f;
    float* ob = out + (size_t)b * L * 64 + o;
    for (int t = threadIdx.x; t < L; t += 1024) {
        float2 c = s[t];
        ob[(size_t)t * 64] += inv * (c.x + ((t & 1) ? -c.y : c.y));
    }
}

// ---------------- launch ----------------
extern "C" void kernel_launch(void* const* d_in, const int* in_sizes, int n_in,
                              void* d_out, int out_size) {
    const float* x   = (const float*)d_in[0];
    const float* phi = (const float*)d_in[1];
    const float* M   = (const float*)d_in[2];
    const float* Mp  = (const float*)d_in[3];
    const float* Mm  = (const float*)d_in[4];
    float* out = (float*)d_out;

    const int FFT_SMEM = (NFFT + 4096) * sizeof(float2);   // 98304

    cudaFuncSetAttribute(k_fwd,   cudaFuncAttributeMaxDynamicSharedMemorySize, FFT_SMEM);
    cudaFuncSetAttribute(k_ifft,  cudaFuncAttributeMaxDynamicSharedMemorySize, FFT_SMEM);
    cudaFuncSetAttribute(k_fused, cudaFuncAttributeMaxDynamicSharedMemorySize, FU_SMEM);

    k_fwd  <<<64 + KF / 2, 1024, FFT_SMEM>>>(x, phi);
    k_fused<<<NEB + ARB,    256, FU_SMEM>>>(Mp, Mm, x, M, out);
    k_ifft <<<2 * 64,      1024, FFT_SMEM>>>(out);
}

// round 14
// speedup vs baseline: 1.4675x; 1.4675x over previous
#include <cuda_runtime.h>
#include <cuda_fp16.h>
#include <math.h>

#define L     4096
#define NF    4097
#define NFFT  8192
#define KF    40
#define FE    32

// ---------------- static device scratch ----------------
__device__ float2 g_Xf[2 * NF * 64];
__device__ float2 g_vf[NF * KF];
__device__ float2 g_Sp[2 * NF * 64];
__device__ float2 g_Sm[2 * NF * 64];

// ---------------- helpers ----------------
__device__ __forceinline__ unsigned brev13(unsigned i) { return __brev(i) >> 19; }
__device__ __forceinline__ unsigned s2u(const void* p) { return (unsigned)__cvta_generic_to_shared(p); }

__device__ __forceinline__ void mma16(float& d0, float& d1, float& d2, float& d3,
                                      unsigned a0, unsigned a1, unsigned a2, unsigned a3,
                                      unsigned b0, unsigned b1) {
    asm("mma.sync.aligned.m16n8k16.row.col.f32.f16.f16.f32 "
        "{%0,%1,%2,%3},{%4,%5,%6,%7},{%8,%9},{%0,%1,%2,%3};"
        : "+f"(d0), "+f"(d1), "+f"(d2), "+f"(d3)
        : "r"(a0), "r"(a1), "r"(a2), "r"(a3), "r"(b0), "r"(b1));
}
__device__ __forceinline__ void ldsm4(unsigned* r, unsigned a) {
    asm volatile("ldmatrix.sync.aligned.m8n8.x4.shared.b16 {%0,%1,%2,%3}, [%4];"
                 : "=r"(r[0]), "=r"(r[1]), "=r"(r[2]), "=r"(r[3]) : "r"(a));
}
__device__ __forceinline__ void ldsm2t(unsigned& r0, unsigned& r1, unsigned a) {
    asm volatile("ldmatrix.sync.aligned.m8n8.x2.trans.shared.b16 {%0,%1}, [%2];"
                 : "=r"(r0), "=r"(r1) : "r"(a));
}

// In-place radix-2 FFT of 8192 (bit-reversed input) with shared twiddle table.
// (Known-good R8 version — radix-4 regressed due to small-stride bank conflicts.)
template<int NT>
__device__ __forceinline__ void fftT(float2* s, const float2* tw) {
    #pragma unroll
    for (int st = 0; st < 13; ++st) {
        const int half = 1 << st, sh = 12 - st;
        for (int j = threadIdx.x; j < 4096; j += NT) {
            int pos = j & (half - 1);
            int i0 = ((j >> st) << (st + 1)) + pos, i1 = i0 + half;
            float2 w = tw[pos << sh];
            float2 u = s[i0], v = s[i1];
            float tr = w.x * v.x - w.y * v.y;
            float ti = w.x * v.y + w.y * v.x;
            s[i0] = make_float2(u.x + tr, u.y + ti);
            s[i1] = make_float2(u.x - tr, u.y - ti);
        }
        __syncthreads();
    }
}

// ---------------- K1: forward FFTs of x (64 blocks) and phi (20 blocks) ----------------
__global__ __launch_bounds__(1024) void k_fwd(const float* __restrict__ x,
                                              const float* __restrict__ phi) {
    extern __shared__ float2 s[];
    float2* tw = s + NFFT;
    for (int i = threadIdx.x; i < 4096; i += 1024) {
        float sv, cv;
        __sincosf(3.14159265358979323846f * (float)i / 4096.0f, &sv, &cv);
        tw[i] = make_float2(cv, -sv);
    }
    const int bb = blockIdx.x;
    const float* src;
    int strd, c0;
    if (bb < 64) { int b = bb >> 5; c0 = (bb & 31) * 2; src = x + (size_t)b * L * 64 + c0; strd = 64; }
    else         { c0 = (bb - 64) * 2; src = phi + c0; strd = KF; }

    for (int i = threadIdx.x; i < NFFT; i += 1024) {
        float2 z = make_float2(0.f, 0.f);
        if (i < L) z = *(const float2*)(src + (size_t)i * strd);
        s[brev13(i)] = z;
    }
    __syncthreads();
    fftT<1024>(s, tw);

    for (int f = threadIdx.x; f <= L; f += 1024) {
        float2 P = s[f], Q = s[(NFFT - f) & (NFFT - 1)];
        float qr = Q.x, qi = -Q.y;
        float4 o = make_float4(0.5f * (P.x + qr), 0.5f * (P.y + qi),
                               0.5f * (P.y - qi), -0.5f * (P.x - qr));
        if (bb < 64) { int b = bb >> 5; *(float4*)&g_Xf[((size_t)b * NF + f) * 64 + c0] = o; }
        else         { *(float4*)&g_vf[(size_t)f * KF + c0] = o; }
    }
}

// ---------------- K2: einsum, 512 threads (two warp-groups split the N dim) ----------------
#define SAH 72
#define SBH 72
#define OFF_AL 18432
#define OFF_B  36864
#define OFF_V  55296
#define EI_SMEM 65536

__global__ __launch_bounds__(512, 1)
void k_einsum(const float* __restrict__ Mp, const float* __restrict__ Mm) {
    extern __shared__ char smc[];
    __half* Ah = (__half*)smc;
    __half* Al = (__half*)(smc + OFF_AL);
    __half* Bs = (__half*)(smc + OFF_B);
    float2* Vs = (float2*)(smc + OFF_V);
    const unsigned smb = s2u(smc);
    const int tid = threadIdx.x, wid = tid >> 5, lane = tid & 31;
    const int w2 = wid & 7;          // row tile 0..7
    const int nh = wid >> 3;         // column half 0/1 (nt 0-3 vs 4-7)
    const int g = lane >> 2, tg = lane & 3;
    const int f0 = blockIdx.x * FE;

    for (int idx = tid; idx < FE * KF; idx += 512) {
        int fl = idx / KF, k = idx - fl * KF, f = f0 + fl;
        Vs[idx] = (f <= L) ? g_vf[(size_t)f * KF + k] : make_float2(0.f, 0.f);
    }

    const int p = 8 * w2 + g, pfl = p & 31, pb = p >> 5, pf = f0 + pfl;
    const unsigned aoff = 2u * ((unsigned)(w2 * 16 + ((lane >> 3) & 1) * 8 + (lane & 7)) * SAH
                                + (unsigned)(lane >> 4) * 8);
    const unsigned brow = (unsigned)((lane & 8) + (lane & 7));

    for (int br = 0; br < 2; ++br) {
        const float* Mb = br ? Mm : Mp;
        __syncthreads();

        // build split-fp16 A in smem
        for (int idx = tid; idx < 4096; idx += 512) {
            int pp = idx >> 6, d = idx & 63;
            int b = pp >> 5, fl = pp & 31, f = f0 + fl;
            float re = 0.f, im = 0.f;
            if (f <= L) {
                float2 X;
                if (br == 0) { X = g_Xf[((size_t)b * NF + f) * 64 + d];       re = X.x; im = X.y;  }
                else         { X = g_Xf[((size_t)b * NF + (L - f)) * 64 + d]; re = X.x; im = -X.y; }
            }
            int rr = ((pp >> 3) << 4) + (pp & 7);
            __half h = __float2half_rn(re);
            Ah[rr * SAH + d] = h;
            Al[rr * SAH + d] = __float2half_rn(re - __half2float(h));
            h = __float2half_rn(im);
            Ah[(rr + 8) * SAH + d] = h;
            Al[(rr + 8) * SAH + d] = __float2half_rn(im - __half2float(h));
        }
        __syncthreads();

        // A fragments (persist across k loop) — both column-half warps load same rows
        unsigned ah[4][4], al[4][4];
        #pragma unroll
        for (int ks = 0; ks < 4; ++ks) {
            ldsm4(ah[ks], smb + aoff + 32u * ks);
            ldsm4(al[ks], smb + OFF_AL + aoff + 32u * ks);
        }

        float S[4][4];
        #pragma unroll
        for (int nt = 0; nt < 4; ++nt)
            S[nt][0] = S[nt][1] = S[nt][2] = S[nt][3] = 0.f;

        // stage B for k=0 into buf0
        #pragma unroll
        for (int i = 0; i < 2; ++i) {
            int e = (tid + i * 512) * 4;
            float4 v4 = *(const float4*)(Mb + e);
            __half2 p0 = __floats2half2_rn(v4.x, v4.y);
            __half2 p1 = __floats2half2_rn(v4.z, v4.w);
            *(uint2*)(Bs + (e >> 6) * SBH + (e & 63)) = make_uint2(*(unsigned*)&p0, *(unsigned*)&p1);
        }
        __syncthreads();

        for (int k = 0; k < KF; ++k) {
            const int cur = k & 1;
            float4 pf4[2];
            if (k + 1 < KF) {
                const float* src2 = Mb + (size_t)(k + 1) * 4096;
                #pragma unroll
                for (int i = 0; i < 2; ++i) pf4[i] = *(const float4*)(src2 + (tid + i * 512) * 4);
            }
            const unsigned bbase = smb + OFF_B + (unsigned)cur * 9216u;
            const float2 v = (pf <= L) ? Vs[pfl * KF + k] : make_float2(0.f, 0.f);

            #pragma unroll
            for (int nt = 0; nt < 4; ++nt) {
                const int ncol = nt + 4 * nh;
                float t0 = 0.f, t1 = 0.f, t2 = 0.f, t3 = 0.f;
                #pragma unroll
                for (int ks = 0; ks < 4; ++ks) {
                    unsigned b0, b1;
                    ldsm2t(b0, b1, bbase + 2u * ((16u * ks + brow) * SBH + 8u * ncol));
                    mma16(t0, t1, t2, t3, ah[ks][0], ah[ks][1], ah[ks][2], ah[ks][3], b0, b1);
                    mma16(t0, t1, t2, t3, al[ks][0], al[ks][1], al[ks][2], al[ks][3], b0, b1);
                }
                S[nt][0] += v.x * t0 - v.y * t2;
                S[nt][1] += v.x * t1 - v.y * t3;
                S[nt][2] += v.x * t2 + v.y * t0;
                S[nt][3] += v.x * t3 + v.y * t1;
            }

            if (k + 1 < KF) {
                __half* Bn = Bs + (cur ^ 1) * 4608;
                #pragma unroll
                for (int i = 0; i < 2; ++i) {
                    int e = (tid + i * 512) * 4;
                    __half2 p0 = __floats2half2_rn(pf4[i].x, pf4[i].y);
                    __half2 p1 = __floats2half2_rn(pf4[i].z, pf4[i].w);
                    *(uint2*)(Bn + (e >> 6) * SBH + (e & 63)) = make_uint2(*(unsigned*)&p0, *(unsigned*)&p1);
                }
            }
            __syncthreads();
        }

        if (pf <= L) {
            float2* Sg = (br ? g_Sm : g_Sp) + ((size_t)pb * NF + pf) * 64;
            #pragma unroll
            for (int nt = 0; nt < 4; ++nt) {
                int o = 8 * (nt + 4 * nh) + 2 * tg;
                Sg[o]     = make_float2(S[nt][0], S[nt][2]);
                Sg[o + 1] = make_float2(S[nt][1], S[nt][3]);
            }
        }
    }
}

// ---------------- K3: inverse FFT; writes out ----------------
__global__ __launch_bounds__(1024) void k_ifft(float* __restrict__ out) {
    extern __shared__ float2 s[];
    float2* tw = s + NFFT;
    for (int i = threadIdx.x; i < 4096; i += 1024) {
        float sv, cv;
        __sincosf(3.14159265358979323846f * (float)i / 4096.0f, &sv, &cv);
        tw[i] = make_float2(cv, sv);
    }
    const int b = blockIdx.x >> 6, o = blockIdx.x & 63;
    const float2* spb = g_Sp + (size_t)b * NF * 64 + o;
    const float2* smb = g_Sm + (size_t)b * NF * 64 + o;

    for (int f = threadIdx.x; f < NFFT; f += 1024) {
        float2 C;
        if (f <= L) {
            float2 p = spb[(size_t)f * 64], m = smb[(size_t)f * 64];
            C = make_float2(p.x - m.y, p.y + m.x);
        } else {
            int gi = NFFT - f;
            float2 p = spb[(size_t)gi * 64], m = smb[(size_t)gi * 64];
            C = make_float2(p.x + m.y, m.x - p.y);
        }
        s[brev13(f)] = C;
    }
    __syncthreads();
    fftT<1024>(s, tw);

    const float inv = 1.0f / 8192.0f;
    float* ob = out + (size_t)b * L * 64 + o;
    for (int t = threadIdx.x; t < L; t += 1024) {
        float2 c = s[t];
        ob[(size_t)t * 64] = inv * (c.x + ((t & 1) ? -c.y : c.y));
    }
}

// ---------------- K4: autoregressive term (256 small blocks, += onto out) ----------------
#define AR_T 32
__global__ __launch_bounds__(256)
void k_ar(const float* __restrict__ x, const float* __restrict__ M, float* __restrict__ out) {
    extern __shared__ float smar[];
    float* Ms = smar;                 // [3][64][64]
    float* xs = smar + 12288;         // [AR_T+2][64]
    const int b  = blockIdx.x >> 7;   // 128 blocks per batch
    const int t0 = (blockIdx.x & 127) * AR_T;
    const int tid = threadIdx.x;

    for (int idx = tid; idx < 12288; idx += 256) {
        int o = idx / 192, r = idx - o * 192;
        int d = r / 3, i = r - d * 3;
        Ms[(i * 64 + d) * 64 + o] = M[idx];
    }
    for (int idx = tid; idx < (AR_T + 2) * 64; idx += 256) {
        int r = idx >> 6, d = idx & 63;
        int t = t0 - 2 + r;
        xs[idx] = (t >= 0) ? x[((size_t)b * L + t) * 64 + d] : 0.f;
    }
    __syncthreads();

    const int o  = tid & 63;
    const int tq = tid >> 6;
    for (int tl = tq; tl < AR_T; tl += 4) {
        const float* x0 = xs + (tl + 2) * 64;
        const float* x1 = x0 - 64;
        const float* x2 = x0 - 128;
        float acc = 0.f;
        #pragma unroll 16
        for (int d = 0; d < 64; ++d) {
            acc += Ms[d * 64 + o]        * x0[d];
            acc += Ms[4096 + d * 64 + o] * x1[d];
            acc += Ms[8192 + d * 64 + o] * x2[d];
        }
        out[((size_t)b * L + t0 + tl) * 64 + o] += acc;
    }
}

// ---------------- launch ----------------
extern "C" void kernel_launch(void* const* d_in, const int* in_sizes, int n_in,
                              void* d_out, int out_size) {
    const float* x   = (const float*)d_in[0];
    const float* phi = (const float*)d_in[1];
    const float* M   = (const float*)d_in[2];
    const float* Mp  = (const float*)d_in[3];
    const float* Mm  = (const float*)d_in[4];
    float* out = (float*)d_out;

    const int FFT_SMEM = (NFFT + 4096) * sizeof(float2);   // 98304
    const int AR_SMEM  = (12288 + (AR_T + 2) * 64) * 4;    // 57856

    cudaFuncSetAttribute(k_fwd,    cudaFuncAttributeMaxDynamicSharedMemorySize, FFT_SMEM);
    cudaFuncSetAttribute(k_ifft,   cudaFuncAttributeMaxDynamicSharedMemorySize, FFT_SMEM);
    cudaFuncSetAttribute(k_ar,     cudaFuncAttributeMaxDynamicSharedMemorySize, AR_SMEM);
    cudaFuncSetAttribute(k_einsum, cudaFuncAttributeMaxDynamicSharedMemorySize, EI_SMEM);

    k_fwd   <<<64 + KF / 2, 1024, FFT_SMEM>>>(x, phi);
    k_einsum<<<(NF + FE - 1) / FE, 512, EI_SMEM>>>(Mp, Mm);
    k_ifft  <<<2 * 64, 1024, FFT_SMEM>>>(out);
    k_ar    <<<2 * 128, 256, AR_SMEM>>>(x, M, out);
}

// round 16
// speedup vs baseline: 1.7718x; 1.2074x over previous
#include <cuda_runtime.h>
#include <cuda_fp16.h>
#include <math.h>

#define L     4096
#define NF    4097
#define NFFT  8192
#define KF    40
#define FE    32

// ---------------- static device scratch ----------------
__device__ float2 g_Xf[2 * NF * 64];
__device__ float2 g_vf[NF * KF];
__device__ float2 g_Sp[2 * NF * 64];
__device__ float2 g_Sm[2 * NF * 64];

// ---------------- helpers ----------------
__device__ __forceinline__ unsigned brev13(unsigned i) { return __brev(i) >> 19; }
__device__ __forceinline__ unsigned s2u(const void* p) { return (unsigned)__cvta_generic_to_shared(p); }

__device__ __forceinline__ float2 cadd(float2 a, float2 b) { return make_float2(a.x + b.x, a.y + b.y); }
__device__ __forceinline__ float2 csub(float2 a, float2 b) { return make_float2(a.x - b.x, a.y - b.y); }
__device__ __forceinline__ float2 cmul(float2 a, float2 b) {
    return make_float2(a.x * b.x - a.y * b.y, a.x * b.y + a.y * b.x);
}

__device__ __forceinline__ void mma16(float& d0, float& d1, float& d2, float& d3,
                                      unsigned a0, unsigned a1, unsigned a2, unsigned a3,
                                      unsigned b0, unsigned b1) {
    asm("mma.sync.aligned.m16n8k16.row.col.f32.f16.f16.f32 "
        "{%0,%1,%2,%3},{%4,%5,%6,%7},{%8,%9},{%0,%1,%2,%3};"
        : "+f"(d0), "+f"(d1), "+f"(d2), "+f"(d3)
        : "r"(a0), "r"(a1), "r"(a2), "r"(a3), "r"(b0), "r"(b1));
}
__device__ __forceinline__ void ldsm4(unsigned* r, unsigned a) {
    asm volatile("ldmatrix.sync.aligned.m8n8.x4.shared.b16 {%0,%1,%2,%3}, [%4];"
                 : "=r"(r[0]), "=r"(r[1]), "=r"(r[2]), "=r"(r[3]) : "r"(a));
}
__device__ __forceinline__ void ldsm2t(unsigned& r0, unsigned& r1, unsigned a) {
    asm volatile("ldmatrix.sync.aligned.m8n8.x2.trans.shared.b16 {%0,%1}, [%2];"
                 : "=r"(r0), "=r"(r1) : "r"(a));
}

// Hybrid-radix in-place FFT of 8192 (bit-reversed input), shared twiddle table.
// Stages 0-4 radix-2 (small strides: radix-4 there causes bank conflicts, R9 lesson);
// stages 5-12 as 4 fused radix-4 passes (strides >=32 float2: conflict-free).
// tw[i] = (cos, SIGN*sin)(pi*i/4096); SIGN=-1 fwd, +1 inv.
template<int NT>
__device__ __forceinline__ void fftH(float2* s, const float2* tw, const float SIGN) {
    #pragma unroll
    for (int st = 0; st < 5; ++st) {
        const int half = 1 << st, sh = 12 - st;
        for (int j = threadIdx.x; j < 4096; j += NT) {
            int pos = j & (half - 1);
            int i0 = ((j >> st) << (st + 1)) + pos, i1 = i0 + half;
            float2 w = tw[pos << sh];
            float2 u = s[i0], v = s[i1];
            float tr = w.x * v.x - w.y * v.y;
            float ti = w.x * v.y + w.y * v.x;
            s[i0] = make_float2(u.x + tr, u.y + ti);
            s[i1] = make_float2(u.x - tr, u.y - ti);
        }
        __syncthreads();
    }
    #pragma unroll
    for (int st = 5; st < 13; st += 2) {
        const int h = 1 << st;
        for (int j = threadIdx.x; j < 2048; j += NT) {
            int pos = j & (h - 1);
            int base = (j >> st) << (st + 2);
            int i0 = base + pos, i1 = i0 + h, i2 = i0 + 2 * h, i3 = i0 + 3 * h;
            float2 t1 = tw[pos << (12 - st)];
            float2 t2 = tw[pos << (11 - st)];
            float2 u0 = s[i0], u1 = s[i1], u2 = s[i2], u3 = s[i3];
            float2 c1 = cmul(t1, u1);
            float2 a0 = cadd(u0, c1), a1 = csub(u0, c1);
            float2 c3 = cmul(t1, u3);
            float2 a2 = cadd(u2, c3), a3 = csub(u2, c3);
            float2 d2 = cmul(t2, a2);
            float2 d3 = cmul(t2, a3);
            float2 d3p = make_float2(-SIGN * d3.y, SIGN * d3.x);
            s[i0] = cadd(a0, d2);  s[i2] = csub(a0, d2);
            s[i1] = cadd(a1, d3p); s[i3] = csub(a1, d3p);
        }
        __syncthreads();
    }
}

// ---------------- K1: forward FFTs of x (64 blocks) and phi (20 blocks) ----------------
__global__ __launch_bounds__(1024) void k_fwd(const float* __restrict__ x,
                                              const float* __restrict__ phi) {
    extern __shared__ float2 s[];
    float2* tw = s + NFFT;
    for (int i = threadIdx.x; i < 4096; i += 1024) {
        float sv, cv;
        __sincosf(3.14159265358979323846f * (float)i / 4096.0f, &sv, &cv);
        tw[i] = make_float2(cv, -sv);
    }
    const int bb = blockIdx.x;
    const float* src;
    int strd, c0;
    if (bb < 64) { int b = bb >> 5; c0 = (bb & 31) * 2; src = x + (size_t)b * L * 64 + c0; strd = 64; }
    else         { c0 = (bb - 64) * 2; src = phi + c0; strd = KF; }

    for (int i = threadIdx.x; i < NFFT; i += 1024) {
        float2 z = make_float2(0.f, 0.f);
        if (i < L) z = *(const float2*)(src + (size_t)i * strd);
        s[brev13(i)] = z;
    }
    __syncthreads();
    fftH<1024>(s, tw, -1.f);

    for (int f = threadIdx.x; f <= L; f += 1024) {
        float2 P = s[f], Q = s[(NFFT - f) & (NFFT - 1)];
        float qr = Q.x, qi = -Q.y;
        float4 o = make_float4(0.5f * (P.x + qr), 0.5f * (P.y + qi),
                               0.5f * (P.y - qi), -0.5f * (P.x - qr));
        if (bb < 64) { int b = bb >> 5; *(float4*)&g_Xf[((size_t)b * NF + f) * 64 + c0] = o; }
        else         { *(float4*)&g_vf[(size_t)f * KF + c0] = o; }
    }
}

// ---------------- K2: einsum, 512 threads (two warp-groups split the N dim) ----------------
#define SAH 72
#define SBH 72
#define OFF_AL 18432
#define OFF_B  36864
#define OFF_V  55296
#define EI_SMEM 65536

__global__ __launch_bounds__(512, 1)
void k_einsum(const float* __restrict__ Mp, const float* __restrict__ Mm) {
    extern __shared__ char smc[];
    __half* Ah = (__half*)smc;
    __half* Al = (__half*)(smc + OFF_AL);
    __half* Bs = (__half*)(smc + OFF_B);
    float2* Vs = (float2*)(smc + OFF_V);
    const unsigned smb = s2u(smc);
    const int tid = threadIdx.x, wid = tid >> 5, lane = tid & 31;
    const int w2 = wid & 7;          // row tile 0..7
    const int nh = wid >> 3;         // column half 0/1
    const int g = lane >> 2, tg = lane & 3;
    const int f0 = blockIdx.x * FE;

    for (int idx = tid; idx < FE * KF; idx += 512) {
        int fl = idx / KF, k = idx - fl * KF, f = f0 + fl;
        Vs[idx] = (f <= L) ? g_vf[(size_t)f * KF + k] : make_float2(0.f, 0.f);
    }

    const int p = 8 * w2 + g, pfl = p & 31, pb = p >> 5, pf = f0 + pfl;
    const unsigned aoff = 2u * ((unsigned)(w2 * 16 + ((lane >> 3) & 1) * 8 + (lane & 7)) * SAH
                                + (unsigned)(lane >> 4) * 8);
    const unsigned brow = (unsigned)((lane & 8) + (lane & 7));

    for (int br = 0; br < 2; ++br) {
        const float* Mb = br ? Mm : Mp;
        __syncthreads();

        for (int idx = tid; idx < 4096; idx += 512) {
            int pp = idx >> 6, d = idx & 63;
            int b = pp >> 5, fl = pp & 31, f = f0 + fl;
            float re = 0.f, im = 0.f;
            if (f <= L) {
                float2 X;
                if (br == 0) { X = g_Xf[((size_t)b * NF + f) * 64 + d];       re = X.x; im = X.y;  }
                else         { X = g_Xf[((size_t)b * NF + (L - f)) * 64 + d]; re = X.x; im = -X.y; }
            }
            int rr = ((pp >> 3) << 4) + (pp & 7);
            __half h = __float2half_rn(re);
            Ah[rr * SAH + d] = h;
            Al[rr * SAH + d] = __float2half_rn(re - __half2float(h));
            h = __float2half_rn(im);
            Ah[(rr + 8) * SAH + d] = h;
            Al[(rr + 8) * SAH + d] = __float2half_rn(im - __half2float(h));
        }
        __syncthreads();

        unsigned ah[4][4], al[4][4];
        #pragma unroll
        for (int ks = 0; ks < 4; ++ks) {
            ldsm4(ah[ks], smb + aoff + 32u * ks);
            ldsm4(al[ks], smb + OFF_AL + aoff + 32u * ks);
        }

        float S[4][4];
        #pragma unroll
        for (int nt = 0; nt < 4; ++nt)
            S[nt][0] = S[nt][1] = S[nt][2] = S[nt][3] = 0.f;

        #pragma unroll
        for (int i = 0; i < 2; ++i) {
            int e = (tid + i * 512) * 4;
            float4 v4 = *(const float4*)(Mb + e);
            __half2 p0 = __floats2half2_rn(v4.x, v4.y);
            __half2 p1 = __floats2half2_rn(v4.z, v4.w);
            *(uint2*)(Bs + (e >> 6) * SBH + (e & 63)) = make_uint2(*(unsigned*)&p0, *(unsigned*)&p1);
        }
        __syncthreads();

        for (int k = 0; k < KF; ++k) {
            const int cur = k & 1;
            float4 pf4[2];
            if (k + 1 < KF) {
                const float* src2 = Mb + (size_t)(k + 1) * 4096;
                #pragma unroll
                for (int i = 0; i < 2; ++i) pf4[i] = *(const float4*)(src2 + (tid + i * 512) * 4);
            }
            const unsigned bbase = smb + OFF_B + (unsigned)cur * 9216u;
            const float2 v = (pf <= L) ? Vs[pfl * KF + k] : make_float2(0.f, 0.f);

            #pragma unroll
            for (int nt = 0; nt < 4; ++nt) {
                const int ncol = nt + 4 * nh;
                float t0 = 0.f, t1 = 0.f, t2 = 0.f, t3 = 0.f;
                #pragma unroll
                for (int ks = 0; ks < 4; ++ks) {
                    unsigned b0, b1;
                    ldsm2t(b0, b1, bbase + 2u * ((16u * ks + brow) * SBH + 8u * ncol));
                    mma16(t0, t1, t2, t3, ah[ks][0], ah[ks][1], ah[ks][2], ah[ks][3], b0, b1);
                    mma16(t0, t1, t2, t3, al[ks][0], al[ks][1], al[ks][2], al[ks][3], b0, b1);
                }
                S[nt][0] += v.x * t0 - v.y * t2;
                S[nt][1] += v.x * t1 - v.y * t3;
                S[nt][2] += v.x * t2 + v.y * t0;
                S[nt][3] += v.x * t3 + v.y * t1;
            }

            if (k + 1 < KF) {
                __half* Bn = Bs + (cur ^ 1) * 4608;
                #pragma unroll
                for (int i = 0; i < 2; ++i) {
                    int e = (tid + i * 512) * 4;
                    __half2 p0 = __floats2half2_rn(pf4[i].x, pf4[i].y);
                    __half2 p1 = __floats2half2_rn(pf4[i].z, pf4[i].w);
                    *(uint2*)(Bn + (e >> 6) * SBH + (e & 63)) = make_uint2(*(unsigned*)&p0, *(unsigned*)&p1);
                }
            }
            __syncthreads();
        }

        if (pf <= L) {
            float2* Sg = (br ? g_Sm : g_Sp) + ((size_t)pb * NF + pf) * 64;
            #pragma unroll
            for (int nt = 0; nt < 4; ++nt) {
                int o = 8 * (nt + 4 * nh) + 2 * tg;
                Sg[o]     = make_float2(S[nt][0], S[nt][2]);
                Sg[o + 1] = make_float2(S[nt][1], S[nt][3]);
            }
        }
    }
}

// ---------------- K3: inverse FFT; writes out ----------------
__global__ __launch_bounds__(1024) void k_ifft(float* __restrict__ out) {
    extern __shared__ float2 s[];
    float2* tw = s + NFFT;
    for (int i = threadIdx.x; i < 4096; i += 1024) {
        float sv, cv;
        __sincosf(3.14159265358979323846f * (float)i / 4096.0f, &sv, &cv);
        tw[i] = make_float2(cv, sv);
    }
    const int b = blockIdx.x >> 6, o = blockIdx.x & 63;
    const float2* spb = g_Sp + (size_t)b * NF * 64 + o;
    const float2* smb = g_Sm + (size_t)b * NF * 64 + o;

    for (int f = threadIdx.x; f < NFFT; f += 1024) {
        float2 C;
        if (f <= L) {
            float2 p = spb[(size_t)f * 64], m = smb[(size_t)f * 64];
            C = make_float2(p.x - m.y, p.y + m.x);
        } else {
            int gi = NFFT - f;
            float2 p = spb[(size_t)gi * 64], m = smb[(size_t)gi * 64];
            C = make_float2(p.x + m.y, m.x - p.y);
        }
        s[brev13(f)] = C;
    }
    __syncthreads();
    fftH<1024>(s, tw, 1.f);

    const float inv = 1.0f / 8192.0f;
    float* ob = out + (size_t)b * L * 64 + o;
    for (int t = threadIdx.x; t < L; t += 1024) {
        float2 c = s[t];
        ob[(size_t)t * 64] = inv * (c.x + ((t & 1) ? -c.y : c.y));
    }
}

// ---------------- K4: AR term — register-tiled, broadcast x, += onto out ----------------
#define AR_T 64
__global__ __launch_bounds__(256)
void k_ar(const float* __restrict__ x, const float* __restrict__ M, float* __restrict__ out) {
    extern __shared__ float smar[];
    float* Ms = smar;                 // [192][64]: Ms[(tap*64+d)*64+o]
    float* xs = smar + 12288;         // transposed: xs[d*67 + r], r = 0..65 (t = t0-2+r)
    const int b  = blockIdx.x >> 6;   // 64 blocks per batch
    const int t0 = (blockIdx.x & 63) * AR_T;
    const int tid = threadIdx.x;

    for (int idx = tid; idx < 12288; idx += 256) {
        int o = idx / 192, r = idx - o * 192;
        int d = r / 3, i = r - d * 3;
        Ms[(i * 64 + d) * 64 + o] = M[idx];
    }
    for (int idx = tid; idx < (AR_T + 2) * 64; idx += 256) {
        int r = idx >> 6, d = idx & 63;
        int t = t0 - 2 + r;
        xs[d * 67 + r] = (t >= 0) ? x[((size_t)b * L + t) * 64 + d] : 0.f;
    }
    __syncthreads();

    const int o  = tid & 63;
    const int tq = tid >> 6;          // 0..3, each covers 16 timesteps
    const int tbase = tq * 16;

    float acc[16];
    #pragma unroll
    for (int i = 0; i < 16; ++i) acc[i] = 0.f;

    #pragma unroll 4
    for (int d = 0; d < 64; ++d) {
        float xv[18];
        #pragma unroll
        for (int j = 0; j < 18; ++j) xv[j] = xs[d * 67 + tbase + j];  // warp-broadcast
        float w0 = Ms[d * 64 + o];
        float w1 = Ms[(64 + d) * 64 + o];
        float w2 = Ms[(128 + d) * 64 + o];
        #pragma unroll
        for (int t = 0; t < 16; ++t)
            acc[t] += w0 * xv[t + 2] + w1 * xv[t + 1] + w2 * xv[t];
    }

    float* ob = out + ((size_t)b * L + t0 + tbase) * 64 + o;
    #pragma unroll
    for (int t = 0; t < 16; ++t) ob[(size_t)t * 64] += acc[t];
}

// ---------------- launch ----------------
extern "C" void kernel_launch(void* const* d_in, const int* in_sizes, int n_in,
                              void* d_out, int out_size) {
    const float* x   = (const float*)d_in[0];
    const float* phi = (const float*)d_in[1];
    const float* M   = (const float*)d_in[2];
    const float* Mp  = (const float*)d_in[3];
    const float* Mm  = (const float*)d_in[4];
    float* out = (float*)d_out;

    const int FFT_SMEM = (NFFT + 4096) * sizeof(float2);       // 98304
    const int AR_SMEM  = (12288 + 64 * 67) * 4;                // 66304

    cudaFuncSetAttribute(k_fwd,    cudaFuncAttributeMaxDynamicSharedMemorySize, FFT_SMEM);
    cudaFuncSetAttribute(k_ifft,   cudaFuncAttributeMaxDynamicSharedMemorySize, FFT_SMEM);
    cudaFuncSetAttribute(k_ar,     cudaFuncAttributeMaxDynamicSharedMemorySize, AR_SMEM);
    cudaFuncSetAttribute(k_einsum, cudaFuncAttributeMaxDynamicSharedMemorySize, EI_SMEM);

    k_fwd   <<<64 + KF / 2, 1024, FFT_SMEM>>>(x, phi);
    k_einsum<<<(NF + FE - 1) / FE, 512, EI_SMEM>>>(Mp, Mm);
    k_ifft  <<<2 * 64, 1024, FFT_SMEM>>>(out);
    k_ar    <<<2 * 64, 256, AR_SMEM>>>(x, M, out);
}